// round 5
// baseline (speedup 1.0000x reference)
#include <cuda_runtime.h>

// LIF neuron scan, T=16:
//   u1 = mem*0.5 + x[t]*0.5 ; spike = (u1 > 1) ; mem = spike ? 0 : u1
// HBM-roofline streaming kernel (512 MB compulsory 1:1 R/W traffic).
// Operating point established over R1-R4:
//   - 1 float4 column per thread, interleaved t-loop (best measured BW:
//     6364 GB/s, DRAM 80.3%)
//   - regs ~32 -> occupancy ~86%+ (warp count supplies MLP; per-thread
//     load batching neutral (R2), occupancy loss fatal (R3))
//   - 32-bit indexing, exact grid, no guard branch
// R5 change: block=128 / 8192 CTAs -> 55.35 waves instead of 27.68,
// halving the partial-wave idle tail.

#define TSTEPS 16

__global__ void __launch_bounds__(128)
lif_scan_kernel(const float* __restrict__ x, float* __restrict__ out)
{
    // Exactly 1,048,576 float4 columns; 8192 CTAs x 128 threads cover them exactly.
    const unsigned col = blockIdx.x * 128u + threadIdx.x;           // 0 .. 2^20-1
    const unsigned stride4 = 1u << 20;                              // float4 cols per timestep

    const float4* __restrict__ xp = reinterpret_cast<const float4*>(x) + col;
    float4* __restrict__ op = reinterpret_cast<float4*>(out) + col;

    float4 mem = make_float4(0.f, 0.f, 0.f, 0.f);

    #pragma unroll
    for (int t = 0; t < TSTEPS; ++t) {
        const unsigned off = (unsigned)t * stride4;
        const float4 xt = xp[off];

        float4 s;
        float u;
        u = fmaf(mem.x, 0.5f, xt.x * 0.5f); s.x = (u > 1.f) ? 1.f : 0.f; mem.x = (u > 1.f) ? 0.f : u;
        u = fmaf(mem.y, 0.5f, xt.y * 0.5f); s.y = (u > 1.f) ? 1.f : 0.f; mem.y = (u > 1.f) ? 0.f : u;
        u = fmaf(mem.z, 0.5f, xt.z * 0.5f); s.z = (u > 1.f) ? 1.f : 0.f; mem.z = (u > 1.f) ? 0.f : u;
        u = fmaf(mem.w, 0.5f, xt.w * 0.5f); s.w = (u > 1.f) ? 1.f : 0.f; mem.w = (u > 1.f) ? 0.f : u;

        op[off] = s;
    }
}

extern "C" void kernel_launch(void* const* d_in, const int* in_sizes, int n_in,
                              void* d_out, int out_size)
{
    const float* x = (const float*)d_in[0];
    float* out = (float*)d_out;

    // 67,108,864 elements / 16 timesteps / 4 per float4 / 128 threads = 8192 CTAs exactly.
    lif_scan_kernel<<<8192, 128>>>(x, out);
}